// round 15
// baseline (speedup 1.0000x reference)
#include <cuda_runtime.h>

#define BB   8
#define QQ   256
#define KK   1024
#define DD   256
#define HH   128
#define DVV  128
#define LOG2E 1.44269504088896340736f

typedef unsigned long long u64;

// Scratch (allocation-free: device globals)
// Ek4 layout: per (b,hq) row of KK float4s; granule of 2 float4s (= 1 k-pair):
//   [h0k0, h0k1, h1k0, h1k1 | h2k0, h2k1, h3k0, h3k1]
// so each aligned u64 lane is an (k0,k1) pack for one h.
__device__ float g_Eq [BB * QQ * HH];        // [b][q][h]   = exp(2*qproj)
__device__ float g_Ek4[BB * (HH/4) * KK * 4];// see layout note above

__device__ __forceinline__ float frcp(float x) {
    float r; asm("rcp.approx.f32 %0, %1;" : "=f"(r) : "f"(x)); return r;
}
__device__ __forceinline__ float fex2(float x) {
    float r; asm("ex2.approx.f32 %0, %1;" : "=f"(r) : "f"(x)); return r;
}
// ---- f32x2 packed helpers (FFMA2: PTX-only, full-rate, IEEE per lane) ----
__device__ __forceinline__ u64 ffma2(u64 a, u64 b, u64 c) {
    u64 d; asm("fma.rn.f32x2 %0, %1, %2, %3;" : "=l"(d) : "l"(a), "l"(b), "l"(c));
    return d;
}
__device__ __forceinline__ u64 fmul2(u64 a, u64 b) {
    u64 d; asm("mul.rn.f32x2 %0, %1, %2;" : "=l"(d) : "l"(a), "l"(b));
    return d;
}
__device__ __forceinline__ u64 dup2(float x) {
    u64 d; asm("mov.b64 %0, {%1, %1};" : "=l"(d) : "f"(x));
    return d;
}
__device__ __forceinline__ float2 unpk(u64 a) {
    float2 f; asm("mov.b64 {%0, %1}, %2;" : "=f"(f.x), "=f"(f.y) : "l"(a));
    return f;
}
__device__ __forceinline__ u64 pk(float x, float y) {
    u64 d; asm("mov.b64 %0, {%1, %2};" : "=l"(d) : "f"(x), "f"(y));
    return d;
}

// ---------------------------------------------------------------------------
// Kernel 1: merged projection + exp. 16 rows per block, 256 threads:
// tid&127 = output column h, tid>>7 = row-half. W native [d][h] (coalesced),
// depth-1 prefetch, f32x2-packed inner loop. K store uses the k-pair layout.
// ---------------------------------------------------------------------------
#define PR 16
__global__ __launch_bounds__(256)
void proj_kernel(const float* __restrict__ Q, const float* __restrict__ Kx,
                 const float* __restrict__ Wq, const float* __restrict__ Wk) {
    __shared__ __align__(16) float xs[PR][DD];     // 16 input rows (16 KB)
    __shared__ float es[HH][PR + 1];               // padded transpose buffer
    int blk  = blockIdx.x;
    bool isK = blk >= (BB * QQ) / PR;              // >= 128
    int rowbase = isK ? (blk - (BB * QQ) / PR) * PR : blk * PR;
    const float* X = isK ? Kx : Q;
    const float* W = isK ? Wk : Wq;
    int tid  = threadIdx.x;
    int h    = tid & 127;                          // output column
    int half = tid >> 7;                           // row-half: 0 or 1
    int r0   = half * 8;                           // first of 8 rows

    {   // coalesced float4 row load (256 threads)
        const float4* Xp = (const float4*)(X + (size_t)rowbase * DD);
        float4* xsp = (float4*)xs;
        for (int i = tid; i < PR * DD / 4; i += 256) xsp[i] = Xp[i];
    }
    __syncthreads();

    u64 acc2[8];
#pragma unroll
    for (int r = 0; r < 8; r++) acc2[r] = 0ull;

    const float* Wp = W + h;
    float w0 = Wp[0 * HH], w1 = Wp[1 * HH], w2 = Wp[2 * HH], w3 = Wp[3 * HH];
    for (int d4 = 0; d4 < DD / 4; d4++) {
        u64 cp01 = pk(w0, w1), cp23 = pk(w2, w3);
        if (d4 + 1 < DD / 4) {                     // prefetch next W quad
            const float* Wn = Wp + (d4 + 1) * 4 * HH;
            w0 = Wn[0 * HH]; w1 = Wn[1 * HH]; w2 = Wn[2 * HH]; w3 = Wn[3 * HH];
        }
        int d = d4 * 4;
#pragma unroll
        for (int r = 0; r < 8; r++) {
            ulonglong2 x2 = *(const ulonglong2*)&xs[r0 + r][d]; // LDS.128
            acc2[r] = ffma2(x2.x, cp01, acc2[r]);
            acc2[r] = ffma2(x2.y, cp23, acc2[r]);
        }
    }

    if (!isK) {
#pragma unroll
        for (int r = 0; r < 8; r++) {
            float2 f = unpk(acc2[r]);
            g_Eq[(rowbase + r0 + r) * HH + h] =
                fex2((f.x + f.y) * (2.0f * LOG2E));
        }
    } else {
#pragma unroll
        for (int r = 0; r < 8; r++) {
            float2 f = unpk(acc2[r]);
            es[h][r0 + r] = fex2((f.x + f.y) * (2.0f * LOG2E));
        }
        __syncthreads();
        int b  = rowbase >> 10;
        int k0 = rowbase & 1023;
        // k-pair interleaved store: float idx within (row,k-pair) granule is
        // h2*2 + (k&1); granule base = (row*KK + k0 + (r&~1)) * 4.
        for (int i = tid; i < HH * PR; i += 256) {
            int hq = i >> 6;              // 64 = PR*4 elements per h-quad
            int r  = (i >> 2) & (PR - 1);
            int h2 = i & 3;
            size_t fi = (((size_t)b * (HH/4) + hq) * KK + k0 + (r & ~1)) * 4
                      + h2 * 2 + (r & 1);
            g_Ek4[fi] = es[hq * 4 + h2][r];
        }
    }
}

// ---------------------------------------------------------------------------
// Kernel 2: fused scores + exp + softmax-denominator + attn@V.
// Block = (b, tile of 2 q-rows), 1024 blocks, 256 threads.
//   s = sum_h (-2 w_h) * rcp(1 + Eq*Ek)   (wsum cancels in softmax)
// LOAD ADDRESSES BYTE-IDENTICAL to the frozen R5 structure.
//  - k-pair granule layout: each loaded u64 lane is an (k0,k1) pack for one
//    h -> zero dup2 MOVs in the loop (eq dups pre-built in smem).
//  - quad-h rcp: 4 MUFU/iter.
//  - NEW (R15): __launch_bounds__(256,5) — mild reg cap 56->51 buys a 5th
//    resident block/SM (occ 45->56%). R9's (256,6) squeeze to 40 was too
//    aggressive; this is the gentle dose.
// ---------------------------------------------------------------------------
#define ONE2 0x3f8000003f800000ull

__global__ __launch_bounds__(256, 5)
void attn_kernel(const float* __restrict__ values,
                 const int*   __restrict__ valid_lens,
                 const float* __restrict__ w_v,
                 float*       __restrict__ out) {
    __shared__ __align__(16) float2 s_eqd[2][HH];      // dup'ed eq, per q
    __shared__ __align__(16) float2 s_w2d[HH];         // dup(-2*w_v[h])
    __shared__ __align__(16) float s_scores[KK * 2];   // exp'ed probs [k][q]
    __shared__ __align__(16) float s_part[8][2][DVV];  // [kgroup][q][v]
    __shared__ float s_red[8][2];
    __shared__ float s_rden[2];

    int b  = blockIdx.x & 7;
    int q0 = (blockIdx.x >> 3) * 2;
    int tid = threadIdx.x;
    int len = valid_lens[b];

    if (tid < HH) {
        float w = -2.0f * w_v[tid];
        s_w2d[tid] = make_float2(w, w);
    }
    if (tid < 2 * HH) {
        int qq = tid >> 7, h = tid & 127;
        float v = g_Eq[((b * QQ) + q0 + qq) * HH + h];
        s_eqd[qq][h] = make_float2(v, v);
    }
    __syncthreads();

    float sum0 = 0.f, sum1 = 0.f;   // denominator partials (q0, q1)

    // ---- main loop: scores + exp (k chunks of 512, 2 k per thread) ----
    for (int kbase = 0; kbase < len; kbase += 512) {
        int k0 = kbase + tid * 2;
        if (k0 < len) {
            u64 accA = 0ull, accB = 0ull;   // (k0,k1) packs for q0 / q1
            // float4 view: same indices as frozen structure
            const float4* ek4 = (const float4*)g_Ek4 + (size_t)b * (HH/4) * KK + k0;
            float4 p0a = ek4[0];            // hq, h0/h1 packs
            float4 p0b = ek4[1];            // hq, h2/h3 packs
            float4 p1a = ek4[KK];           // hq+1
            float4 p1b = ek4[KK + 1];
#pragma unroll 2
            for (int hq = 0; hq < HH / 4; hq++) {
                float4 ca = p0a, cb = p0b;
                p0a = p1a; p0b = p1b;
                int hn = (hq + 2) & (HH / 4 - 1);     // wrap: harmless reload
                p1a = ek4[(size_t)hn * KK];
                p1b = ek4[(size_t)hn * KK + 1];
                int h = hq * 4;
                // ek (k0,k1) packs per h — straight from the loads, no dup
                u64 ek0 = ((const u64*)&ca)[0];
                u64 ek1 = ((const u64*)&ca)[1];
                u64 ek2 = ((const u64*)&cb)[0];
                u64 ek3 = ((const u64*)&cb)[1];
                // w dups (LDS.128 x2)
                float4 w4a = *(const float4*)&s_w2d[h];
                float4 w4b = *(const float4*)&s_w2d[h + 2];
                u64 w0 = ((const u64*)&w4a)[0];
                u64 w1 = ((const u64*)&w4a)[1];
                u64 w2 = ((const u64*)&w4b)[0];
                u64 w3 = ((const u64*)&w4b)[1];
#pragma unroll
                for (int qq = 0; qq < 2; qq++) {
                    // eq dups (LDS.128 x2 per q)
                    float4 e4a = *(const float4*)&s_eqd[qq][h];
                    float4 e4b = *(const float4*)&s_eqd[qq][h + 2];
                    u64 e0 = ((const u64*)&e4a)[0];
                    u64 e1 = ((const u64*)&e4a)[1];
                    u64 e2 = ((const u64*)&e4b)[0];
                    u64 e3 = ((const u64*)&e4b)[1];
                    u64 E1 = ffma2(ek0, e0, ONE2);
                    u64 E2 = ffma2(ek1, e1, ONE2);
                    u64 E3 = ffma2(ek2, e2, ONE2);
                    u64 E4 = ffma2(ek3, e3, ONE2);
                    u64 P12 = fmul2(E1, E2);
                    u64 P34 = fmul2(E3, E4);
                    u64 n12 = ffma2(w0, E2, fmul2(w1, E1));
                    u64 n34 = ffma2(w2, E4, fmul2(w3, E3));
                    u64 nt  = ffma2(n12, P34, fmul2(n34, P12));
                    float2 pf = unpk(fmul2(P12, P34));
                    u64 R = pk(frcp(pf.x), frcp(pf.y));
                    if (qq == 0) accA = ffma2(nt, R, accA);
                    else         accB = ffma2(nt, R, accB);
                }
            }
            float2 f0 = unpk(accA);         // (score k0 q0, score k1 q0)
            float2 f1 = unpk(accB);         // (score k0 q1, score k1 q1)
            // exp (no max subtraction needed: |score| <= ~18)
            float pA0 = fex2(f0.x * LOG2E);
            float pA1 = fex2(f1.x * LOG2E);
            float pB0 = fex2(f0.y * LOG2E);
            float pB1 = fex2(f1.y * LOG2E);
            *(float4*)&s_scores[k0 * 2] = make_float4(pA0, pA1, pB0, pB1);
            bool two = (k0 + 1 < len);
            if (!two) { pB0 = 0.f; pB1 = 0.f; }   // guard odd len tail
            sum0 += pA0 + pB0;
            sum1 += pA1 + pB1;
        }
    }
    // NOTE: if len is odd, s_scores[len] was written but AV reads only k<len.

    // ---- denominator reduction ----
    int warp = tid >> 5, lane = tid & 31;
    for (int o = 16; o > 0; o >>= 1) {
        sum0 += __shfl_xor_sync(0xffffffffu, sum0, o);
        sum1 += __shfl_xor_sync(0xffffffffu, sum1, o);
    }
    if (lane == 0) { s_red[warp][0] = sum0; s_red[warp][1] = sum1; }
    __syncthreads();
    if (tid < 2) {
        float s = 0.f;
        for (int w = 0; w < 8; w++) s += s_red[w][tid];
        s_rden[tid] = frcp(s);
    }
    __syncthreads();

    // ---- attn @ V  (8 k-groups x 32 lanes, float4 V loads, f32x2 FMA) ----
    int g = warp;              // k-group = warp (0..7)
    int l = lane;              // v quad index: v0 = 4*l
    u64 a00 = 0ull, a01 = 0ull;   // q0: (v0,v1), (v2,v3)
    u64 a10 = 0ull, a11 = 0ull;   // q1
    const ulonglong2* Vp = (const ulonglong2*)(values + (size_t)b * KK * DVV) + l;
    for (int k = g; k < len; k += 8) {
        float2 p = *(const float2*)&s_scores[k * 2];
        ulonglong2 v = Vp[k * (DVV / 4)];
        u64 px = dup2(p.x), py = dup2(p.y);
        a00 = ffma2(px, v.x, a00); a01 = ffma2(px, v.y, a01);
        a10 = ffma2(py, v.x, a10); a11 = ffma2(py, v.y, a11);
    }
    *(u64*)&s_part[g][0][4 * l]     = a00;
    *(u64*)&s_part[g][0][4 * l + 2] = a01;
    *(u64*)&s_part[g][1][4 * l]     = a10;
    *(u64*)&s_part[g][1][4 * l + 2] = a11;
    __syncthreads();

    {
        int qq = tid >> 7;
        int v  = tid & 127;
        float rd = s_rden[qq];
        float o = ((s_part[0][qq][v] + s_part[1][qq][v])
                 + (s_part[2][qq][v] + s_part[3][qq][v]))
                + ((s_part[4][qq][v] + s_part[5][qq][v])
                 + (s_part[6][qq][v] + s_part[7][qq][v]));
        out[((size_t)(b * QQ + q0 + qq)) * DVV + v] = o * rd;
    }
}

extern "C" void kernel_launch(void* const* d_in, const int* in_sizes, int n_in,
                              void* d_out, int out_size) {
    const float* queries = (const float*)d_in[0];   // [8,256,256]
    const float* keys    = (const float*)d_in[1];   // [8,1024,256]
    const float* values  = (const float*)d_in[2];   // [8,1024,128]
    const int*   vlens   = (const int*)  d_in[3];   // [8]
    const float* W_q     = (const float*)d_in[4];   // [256,128]
    const float* W_k     = (const float*)d_in[5];   // [256,128]
    const float* w_v     = (const float*)d_in[6];   // [128]
    float* out = (float*)d_out;                     // [8,256,128]

    proj_kernel<<<(BB * QQ + BB * KK) / PR, 256>>>(queries, keys, W_q, W_k);
    attn_kernel<<<BB * (QQ / 2), 256>>>(values, vlens, w_v, out);
}